// round 16
// baseline (speedup 1.0000x reference)
#include <cuda_runtime.h>
#include <stdint.h>

typedef unsigned long long u64;
typedef unsigned int u32;

// Problem shape (fixed by the dataset)
constexpr int B       = 4;
constexpr int N       = 32768;
constexpr int NQ      = 2048;
constexpr int K       = 16;
constexpr int QSTRIDE = N / NQ;   // 16

// Spatial grid: h = 0.25 (power of two -> exact cell boundaries), covering
// [-5, 5)^3; coordinates outside are clamped into edge cells (their stored
// coords stay exact, so distances and the pruning bound remain valid).
constexpr int   G    = 40;
constexpr int   NC   = G * G * G;       // 64000 cells
constexpr float XMIN = -5.0f;
constexpr float H    = 0.25f;
constexpr float INVH = 4.0f;

constexpr u64 KEY_INF = ~0ULL;
constexpr u32 FULL    = 0xffffffffu;

// Device scratch (static allocation -- no cudaMalloc anywhere)
__device__ float4 g_pts[B][N];          // cell-sorted points, w = idx bits
__device__ u32    g_count[B][NC];
__device__ u32    g_start[B][NC + 1];
__device__ u32    g_cursor[B][NC];

__device__ __forceinline__ int cellof(float v) {
    int c = (int)floorf((v - XMIN) * INVH);
    return min(max(c, 0), G - 1);
}

__device__ __forceinline__ u64 pk(u32 lo, u32 hi) {
    u64 r; asm("mov.b64 %0, {%1, %2};" : "=l"(r) : "r"(lo), "r"(hi)); return r;
}

// ---------------- build kernels (unchanged, proven) ----------------

__global__ void zero_kernel() {
    int i = blockIdx.x * blockDim.x + threadIdx.x;
    if (i < B * NC) ((u32*)g_count)[i] = 0;
}

__global__ void hist_kernel(const float* __restrict__ xyz) {
    int i = blockIdx.x * blockDim.x + threadIdx.x;
    if (i >= B * N) return;
    int b = i >> 15, p = i & (N - 1);
    const float* q = xyz + (size_t)b * N * 3 + (size_t)p * 3;
    int c = (cellof(q[2]) * G + cellof(q[1])) * G + cellof(q[0]);
    atomicAdd(&g_count[b][c], 1u);
}

__global__ void scan_kernel() {
    const int b = blockIdx.x;
    const int t = threadIdx.x;
    const int IT = (NC + 1023) / 1024;      // 63
    const int s0 = t * IT;
    const int s1 = min(s0 + IT, NC);

    u32 sum = 0;
    for (int i = s0; i < s1; ++i) sum += g_count[b][i];

    __shared__ u32 sh[1024];
    sh[t] = sum;
    __syncthreads();
    for (int off = 1; off < 1024; off <<= 1) {
        u32 v = 0;
        if (t >= off) v = sh[t - off];
        __syncthreads();
        if (t >= off) sh[t] += v;
        __syncthreads();
    }
    u32 prefix = (t > 0) ? sh[t - 1] : 0;    // exclusive prefix of my chunk
    for (int i = s0; i < s1; ++i) {
        g_start[b][i]  = prefix;
        g_cursor[b][i] = prefix;
        prefix += g_count[b][i];
    }
    if (t == 0) g_start[b][NC] = sh[1023];
}

__global__ void scatter_kernel(const float* __restrict__ xyz) {
    int i = blockIdx.x * blockDim.x + threadIdx.x;
    if (i >= B * N) return;
    int b = i >> 15, p = i & (N - 1);
    const float* q = xyz + (size_t)b * N * 3 + (size_t)p * 3;
    float x = q[0], y = q[1], z = q[2];
    int c = (cellof(z) * G + cellof(y)) * G + cellof(x);
    u32 pos = atomicAdd(&g_cursor[b][c], 1u);
    g_pts[b][pos] = make_float4(x, y, z, __uint_as_float((u32)p));
}

// ---------------- exact top-K machinery (proven) ----------

// Insert up to 32 candidate keys (nk; invalid lanes = KEY_INF, mask m) into
// the warp-distributed sorted list L (lane i holds element i, ascending).
__device__ __forceinline__ void warp_insert(u64& L, u64 nk, u32 m, int lane) {
    if (__popc(m) <= 2) {
        while (m) {                        // 1-2 keys: distributed shift-insert
            const int src = __ffs(m) - 1;
            m &= m - 1;
            const u64 k  = __shfl_sync(FULL, nk, src);
            const u64 up = __shfl_up_sync(FULL, L, 1);
            if (k < L) L = (lane > 0 && k < up) ? up : k;
        }
    } else {
        // Bitonic sort 32 candidates ascending.
#pragma unroll
        for (int k2 = 2; k2 <= 32; k2 <<= 1) {
#pragma unroll
            for (int j2 = k2 >> 1; j2 >= 1; j2 >>= 1) {
                const u64 o = __shfl_xor_sync(FULL, nk, j2);
                const bool takemin = ((lane & j2) == 0) == ((lane & k2) == 0);
                const bool pl = nk < o;
                nk = (pl == takemin) ? nk : o;
            }
        }
        // Old (asc) vs new reversed (desc): min -> bitonic of 32 smallest.
        const u64 r = __shfl_sync(FULL, nk, 31 - lane);
        L = (L < r) ? L : r;
#pragma unroll
        for (int j2 = 16; j2 >= 1; j2 >>= 1) {
            const u64 o = __shfl_xor_sync(FULL, L, j2);
            const bool takemin = ((lane & j2) == 0);
            const bool pl = L < o;
            L = (pl == takemin) ? L : o;
        }
    }
}

// Scan a contiguous run [s, e) of cell-sorted points against one query.
// 4 candidates per lane per iteration: 4 independent LDG.128 in flight
// (hides L2 latency), ONE warp vote per 128 candidates on the fast path.
// No loop-control vote (count is warp-uniform). Distances bit-exact fp32;
// u64 key order == jax.lax.top_k's (d asc, idx asc).
__device__ __forceinline__ void scan_span(const float4* __restrict__ pts,
                                          u32 s, u32 e,
                                          float qx, float qy, float qz,
                                          int lane, u64& L, u64& T, u32& Th) {
    const int cnt = (int)(e - s);
    for (int base = 0; base < cnt; base += 128) {
        u32 db[4], pi[4];
        bool any = false;
#pragma unroll
        for (int k = 0; k < 4; ++k) {
            const int idx = base + k * 32 + lane;
            db[k] = FULL;          // inactive -> full KEY_INF key (both words;
            pi[k] = FULL;          //  a half-sentinel would pass the exact test)
            if (idx < cnt) {
                const float4 p = pts[s + idx];
                const float dx = __fsub_rn(qx, p.x);
                const float dy = __fsub_rn(qy, p.y);
                const float dz = __fsub_rn(qz, p.z);
                const float d  = __fadd_rn(__fadd_rn(__fmul_rn(dx, dx),
                                                     __fmul_rn(dy, dy)),
                                           __fmul_rn(dz, dz));
                db[k] = __float_as_uint(d);
                pi[k] = __float_as_uint(p.w);
                // d >= 0: float order == unsigned order. <= because an equal
                // distance can still win on smaller index.
                any |= (db[k] <= Th);
            }
        }
        if (__any_sync(FULL, any)) {
#pragma unroll
            for (int k = 0; k < 4; ++k) {
                const u64 ck = pk(pi[k], db[k]);
                const bool v = ck < T;          // exact lexicographic test
                const u32 m = __ballot_sync(FULL, v);
                if (m) {
                    warp_insert(L, v ? ck : KEY_INF, m, lane);
                    T  = __shfl_sync(FULL, L, K - 1);
                    Th = (u32)(T >> 32);
                }
            }
        }
    }
}

// ---------------- query kernel ----------------

constexpr int QWARPS_PER_BLOCK = 8;
constexpr int QTHREADS = QWARPS_PER_BLOCK * 32;   // 256

__global__ __launch_bounds__(QTHREADS)
void query_kernel(const float* __restrict__ xyz, float* __restrict__ out) {
    const int lane = threadIdx.x & 31;
    const int warp = threadIdx.x >> 5;
    const int qg   = blockIdx.x * QWARPS_PER_BLOCK + warp;
    const int b    = qg >> 11;                    // / NQ
    const int q    = qg & (NQ - 1);

    const float* __restrict__ base = xyz + (size_t)b * N * 3;
    const int qidx = q * QSTRIDE;
    const float qx = base[qidx * 3 + 0];
    const float qy = base[qidx * 3 + 1];
    const float qz = base[qidx * 3 + 2];

    const int cx = cellof(qx), cy = cellof(qy), cz = cellof(qz);

    const float4* __restrict__ pts = g_pts[b];
    const u32*    __restrict__ st  = g_start[b];

    u64 L = KEY_INF, T = KEY_INF;
    u32 Th = FULL;

    // Scan one x-contiguous row of cells [x0, x1] at (zz, yy).
    auto row = [&](int zz, int yy, int x0, int x1) {
        x0 = max(x0, 0);
        x1 = min(x1, G - 1);
        if (x0 > x1) return;
        const int rb = (zz * G + yy) * G;
        const u32 s = __ldg(&st[rb + x0]);
        const u32 e = __ldg(&st[rb + x1 + 1]);
        if (s < e) scan_span(pts, s, e, qx, qy, qz, lane, L, T, Th);
    };

    // Phase A: full box of Chebyshev radius 1 (27 cells, 9 rows).
    for (int dz = -1; dz <= 1; ++dz) {
        const int zz = cz + dz;
        if (zz < 0 || zz >= G) continue;
        for (int dy = -1; dy <= 1; ++dy) {
            const int yy = cy + dy;
            if (yy < 0 || yy >= G) continue;
            row(zz, yy, cx - 1, cx + 1);
        }
    }

    // Phase B: expand rings while unscanned cells could hold a better key.
    for (int r = 1; r < G; ++r) {
        // Conservative lower bound on the distance from q to any point in a
        // cell OUTSIDE the box of radius r. Cell boundaries XMIN + k*H are
        // exact fp32; round-down subs give a true lower bound; the 1e-5
        // margin covers boundary-assignment rounding fuzz (~1e-6).
        const float lox = XMIN + (float)(cx - r) * H;
        const float hix = XMIN + (float)(cx + r + 1) * H;
        const float loy = XMIN + (float)(cy - r) * H;
        const float hiy = XMIN + (float)(cy + r + 1) * H;
        const float loz = XMIN + (float)(cz - r) * H;
        const float hiz = XMIN + (float)(cz + r + 1) * H;
        float m = fminf(__fsub_rd(qx, lox), __fsub_rd(hix, qx));
        m = fminf(m, fminf(__fsub_rd(qy, loy), __fsub_rd(hiy, qy)));
        m = fminf(m, fminf(__fsub_rd(qz, loz), __fsub_rd(hiz, qz)));
        m = __fsub_rd(m, 1e-5f);
        if (m > 0.0f) {
            const float b2 = __fmul_rd(m, m);
            // Strict >: equal-distance unscanned points (which could win a
            // tie on index) keep the scan going. Th == 0xFFFFFFFF (unfilled
            // sentinel) can never satisfy it.
            if (__float_as_uint(b2) > Th) break;
        }
        // Scan ring r+1 (cells at Chebyshev distance exactly r+1).
        const int rr = r + 1;
        for (int dz = -rr; dz <= rr; ++dz) {
            const int zz = cz + dz;
            if (zz < 0 || zz >= G) continue;
            const bool zedge = (dz == -rr) || (dz == rr);
            for (int dy = -rr; dy <= rr; ++dy) {
                const int yy = cy + dy;
                if (yy < 0 || yy >= G) continue;
                if (zedge || dy == -rr || dy == rr) {
                    row(zz, yy, cx - rr, cx + rr);        // full row
                } else {
                    row(zz, yy, cx - rr, cx - rr);        // two x-end cells
                    row(zz, yy, cx + rr, cx + rr);
                }
            }
        }
    }

    // Output 0: idx (B, NQ, K, 1) as fp32 (values < 2^15, exact).
    // Output 1: pts (B, NQ, 3) fp32.
    float* __restrict__ out_idx = out;
    float* __restrict__ out_pts = out + (size_t)B * NQ * K;

    if (lane < K)
        out_idx[(size_t)qg * K + lane] = (float)(u32)(L & 0xffffffffu);
    if (lane == 0) {
        out_pts[(size_t)qg * 3 + 0] = qx;
        out_pts[(size_t)qg * 3 + 1] = qy;
        out_pts[(size_t)qg * 3 + 2] = qz;
    }
}

// ---------------- launch ----------------

extern "C" void kernel_launch(void* const* d_in, const int* in_sizes, int n_in,
                              void* d_out, int out_size) {
    (void)in_sizes; (void)n_in; (void)out_size;
    const float* xyz = (const float*)d_in[0];
    float* out = (float*)d_out;

    zero_kernel<<<(B * NC + 255) / 256, 256>>>();
    hist_kernel<<<(B * N + 255) / 256, 256>>>(xyz);
    scan_kernel<<<B, 1024>>>();
    scatter_kernel<<<(B * N + 255) / 256, 256>>>(xyz);
    query_kernel<<<(B * NQ) / QWARPS_PER_BLOCK, QTHREADS>>>(xyz, out);
}